// round 8
// baseline (speedup 1.0000x reference)
#include <cuda_runtime.h>
#include <cstdint>

#define N_NODES 100000
#define N_EDGES 1600000
#define D 128

// Scratch (allocation-free: __device__ globals, zero-initialized).
// IMPORTANT: these are referenced ONLY inside device code — passing them as
// kernel arguments from host code yields the host-side shadow address
// (silently wrong on GB300 due to ATS). That was the R3-R6 bug.
__device__ float g_Y[(size_t)N_NODES * D];   // X @ W
__device__ float g_deg[N_NODES];
__device__ int   g_idx_is64;                 // adjacency dtype flag

// ---------------------------------------------------------------------------
// K_detect: int64 vs int32 adjacency. int64 values < 2^32 -> every odd
// 32-bit word is 0; int32 -> odd words are random node ids (all-zero across
// 64 samples: p ~ 1e-320). Deterministic for fixed inputs.
// ---------------------------------------------------------------------------
__global__ void detect_kernel(const unsigned int* __restrict__ adj_raw) {
    if (threadIdx.x == 0 && blockIdx.x == 0) {
        int is64 = 1;
        for (int i = 1; i < 128; i += 2)
            if (adj_raw[i] != 0u) { is64 = 0; break; }
        g_idx_is64 = is64;
    }
}

// ---------------------------------------------------------------------------
// K0: zero the output accumulator and degree array (d_out is poisoned 0xAA)
// ---------------------------------------------------------------------------
__global__ void zero_kernel(float* __restrict__ out) {
    const int total4 = (N_NODES * D) / 4;   // 3.2M float4
    float4 z = make_float4(0.f, 0.f, 0.f, 0.f);
    int stride = gridDim.x * blockDim.x;
    for (int i = blockIdx.x * blockDim.x + threadIdx.x; i < total4; i += stride)
        reinterpret_cast<float4*>(out)[i] = z;
    for (int i = blockIdx.x * blockDim.x + threadIdx.x; i < N_NODES; i += stride)
        g_deg[i] = 0.f;
}

// ---------------------------------------------------------------------------
// K1: g_Y = X @ W, K-tiled, static smem (~21KB).
//   256 threads = 32 rows x 8 col-groups; thread (r,cg) computes 16 cols of
//   row r: cols { 4*cg + 32*jj + 0..3 }. sW chunk [32][128] (16KB), sX chunk
//   [32][36] (pad -> conflict-free row broadcast).
// Writes g_Y by direct device-code symbol reference.
// ---------------------------------------------------------------------------
#define KCHUNK 32
#define XPAD 36
__global__ __launch_bounds__(256)
void gemm_kernel(const float* __restrict__ X, const float* __restrict__ W) {
    __shared__ float sW[KCHUNK * D];      // 16384 B
    __shared__ float sX[32 * XPAD];       //  4608 B

    const int tid  = threadIdx.x;
    const int row0 = blockIdx.x * 32;
    const int r    = tid >> 3;   // 0..31 row within tile
    const int cg   = tid & 7;    // 0..7 column group

    float acc[16];
#pragma unroll
    for (int j = 0; j < 16; j++) acc[j] = 0.f;

    for (int kt = 0; kt < D; kt += KCHUNK) {
        // W chunk: rows kt..kt+31, all 128 cols = 1024 float4
        for (int i = tid; i < (KCHUNK * D) / 4; i += 256)
            reinterpret_cast<float4*>(sW)[i] =
                reinterpret_cast<const float4*>(W + (size_t)kt * D)[i];
        // X chunk: 32 rows x 32 k-values (1 float4 per thread)
        {
            int rr = tid >> 3;         // 0..31
            int c4 = tid & 7;          // 0..7
            float4 xv = reinterpret_cast<const float4*>(
                X + (size_t)(row0 + rr) * D + kt)[c4];
            sX[rr * XPAD + c4 * 4 + 0] = xv.x;
            sX[rr * XPAD + c4 * 4 + 1] = xv.y;
            sX[rr * XPAD + c4 * 4 + 2] = xv.z;
            sX[rr * XPAD + c4 * 4 + 3] = xv.w;
        }
        __syncthreads();

        const float* xrow = sX + r * XPAD;
#pragma unroll
        for (int kk = 0; kk < KCHUNK; kk++) {
            float xv = xrow[kk];
            const float4* wk = reinterpret_cast<const float4*>(sW + kk * D);
#pragma unroll
            for (int jj = 0; jj < 4; jj++) {
                float4 w = wk[cg + jj * 8];   // cols 4cg + 32jj .. +3
                acc[jj * 4 + 0] += xv * w.x;
                acc[jj * 4 + 1] += xv * w.y;
                acc[jj * 4 + 2] += xv * w.z;
                acc[jj * 4 + 3] += xv * w.w;
            }
        }
        __syncthreads();
    }

    float* yrow = g_Y + (size_t)(row0 + r) * D;   // device-side symbol ref
#pragma unroll
    for (int jj = 0; jj < 4; jj++) {
        float4 v = make_float4(acc[jj * 4 + 0], acc[jj * 4 + 1],
                               acc[jj * 4 + 2], acc[jj * 4 + 3]);
        reinterpret_cast<float4*>(yrow)[cg + jj * 8] = v;
    }
}

// ---------------------------------------------------------------------------
// K2: edge scatter. One warp per edge: gather g_Y[dst] (one float4 per lane,
// 512B row, L2-resident) and vector-reduce into out[src]. Lane 0 bumps
// degree. Out-of-range indices skipped (safety net).
// ---------------------------------------------------------------------------
__global__ __launch_bounds__(256)
void scatter_kernel(const void* __restrict__ adj,
                    float* __restrict__ out) {
    int gw   = (blockIdx.x * blockDim.x + threadIdx.x) >> 5;
    int lane = threadIdx.x & 31;
    if (gw >= N_EDGES) return;

    long long s, d;
    if (g_idx_is64) {
        const long long* a = (const long long*)adj;
        s = __ldg(a + gw);
        d = __ldg(a + N_EDGES + gw);
    } else {
        const int* a = (const int*)adj;
        s = __ldg(a + gw);
        d = __ldg(a + N_EDGES + gw);
    }
    if ((unsigned long long)s >= N_NODES || (unsigned long long)d >= N_NODES)
        return;

    float4 v = reinterpret_cast<const float4*>(g_Y + (size_t)d * D)[lane];
    float* p = out + (size_t)s * D + lane * 4;
    asm volatile("red.global.add.v4.f32 [%0], {%1, %2, %3, %4};"
                 :: "l"(p), "f"(v.x), "f"(v.y), "f"(v.z), "f"(v.w)
                 : "memory");

    if (lane == 0)
        atomicAdd(g_deg + s, 1.0f);
}

// ---------------------------------------------------------------------------
// K3: out[n, :] /= max(deg[n], 1)
// ---------------------------------------------------------------------------
__global__ __launch_bounds__(256)
void divide_kernel(float* __restrict__ out) {
    const int total4 = (N_NODES * D) / 4;
    int i = blockIdx.x * blockDim.x + threadIdx.x;
    if (i >= total4) return;
    int n = i >> 5;                   // 32 float4 per row
    float inv = 1.0f / fmaxf(g_deg[n], 1.0f);
    float4 v = reinterpret_cast<float4*>(out)[i];
    v.x *= inv; v.y *= inv; v.z *= inv; v.w *= inv;
    reinterpret_cast<float4*>(out)[i] = v;
}

// ---------------------------------------------------------------------------
extern "C" void kernel_launch(void* const* d_in, const int* in_sizes, int n_in,
                              void* d_out, int out_size) {
    // Identify inputs by element count — robust to any metadata ordering.
    //   input_matrix : 100000*128  = 12,800,000
    //   adjacency    : 2*1,600,000 =  3,200,000 (dtype-independent)
    //   weights      : 128*128     =     16,384
    const float* X   = nullptr;
    const void*  adj = nullptr;
    const float* W   = nullptr;
    for (int i = 0; i < n_in; i++) {
        if (in_sizes[i] == N_NODES * D)      X   = (const float*)d_in[i];
        else if (in_sizes[i] == 2 * N_EDGES) adj = d_in[i];
        else if (in_sizes[i] == D * D)       W   = (const float*)d_in[i];
    }
    float* out = (float*)d_out;

    // Detect adjacency dtype (device-side; graph-capturable)
    detect_kernel<<<1, 32>>>((const unsigned int*)adj);

    // K0: zero out + deg
    zero_kernel<<<2048, 256>>>(out);

    // K1: g_Y = X @ W (writes scratch via device-side symbol)
    gemm_kernel<<<N_NODES / 32, 256>>>(X, W);

    // K2: scatter-add g_Y[dst] into out[src], count degrees
    {
        long long total_threads = (long long)N_EDGES * 32;
        int blocks = (int)((total_threads + 255) / 256);
        scatter_kernel<<<blocks, 256>>>(adj, out);
    }

    // K3: divide by degree
    {
        int total4 = (N_NODES * D) / 4;
        divide_kernel<<<(total4 + 255) / 256, 256>>>(out);
    }
}

// round 10
// speedup vs baseline: 2.0353x; 2.0353x over previous
#include <cuda_runtime.h>
#include <cstdint>

#define N_NODES 100000
#define N_EDGES 1600000
#define D 128
#define SCAN_CHUNK 1024
#define NSCAN_BLK ((N_NODES + SCAN_CHUNK - 1) / SCAN_CHUNK)   // 98

typedef unsigned long long u64;

// Scratch — device-code references ONLY (host-arg shadow-address bug, R3-R6).
__device__ float g_Y[(size_t)N_NODES * D];   // X @ W
__device__ int   g_cnt[N_NODES];             // degree histogram
__device__ int   g_rowptr[N_NODES];          // CSR row starts (exclusive scan)
__device__ int   g_wp[N_NODES];              // fill write pointers
__device__ int   g_dst[N_EDGES];             // dst indices grouped by src
__device__ int   g_bsum[NSCAN_BLK];
__device__ int   g_btop[NSCAN_BLK];
__device__ int   g_idx_is64;

// Packed-f32 FMA (B300 FFMA2 — only reachable via PTX)
#define PACK_DUP(dst, x) \
    asm("mov.b64 %0, {%1, %1};" : "=l"(dst) : "f"(x))
#define FMA2(d, a, b, c) \
    asm("fma.rn.f32x2 %0, %1, %2, %3;" : "=l"(d) : "l"(a), "l"(b), "l"(c))

// ---------------------------------------------------------------------------
// dtype detect: int64 values < 2^32 -> all odd 32-bit words are 0.
// ---------------------------------------------------------------------------
__global__ void detect_kernel(const unsigned int* __restrict__ adj_raw) {
    if (threadIdx.x == 0 && blockIdx.x == 0) {
        int is64 = 1;
        for (int i = 1; i < 128; i += 2)
            if (adj_raw[i] != 0u) { is64 = 0; break; }
        g_idx_is64 = is64;
    }
}

// ---------------------------------------------------------------------------
// CSR build stage 1: zero counters, histogram src degrees
// ---------------------------------------------------------------------------
__global__ void zero_cnt_kernel() {
    int i = blockIdx.x * blockDim.x + threadIdx.x;
    if (i < N_NODES) g_cnt[i] = 0;
}

__global__ __launch_bounds__(256)
void hist_kernel(const void* __restrict__ adj) {
    int e = blockIdx.x * blockDim.x + threadIdx.x;
    if (e >= N_EDGES) return;
    long long s = g_idx_is64 ? __ldg((const long long*)adj + e)
                             : (long long)__ldg((const int*)adj + e);
    if ((unsigned long long)s < N_NODES)
        atomicAdd(&g_cnt[(int)s], 1);
}

// ---------------------------------------------------------------------------
// CSR build stage 2: exclusive scan of g_cnt (3 kernels)
// ---------------------------------------------------------------------------
__global__ __launch_bounds__(256)
void scan_block_kernel() {
    __shared__ int wsum[8];
    int b = blockIdx.x, t = threadIdx.x;
    int i0 = b * SCAN_CHUNK + t * 4;
    int s = 0;
#pragma unroll
    for (int j = 0; j < 4; j++)
        s += (i0 + j < N_NODES) ? g_cnt[i0 + j] : 0;
    for (int off = 16; off; off >>= 1)
        s += __shfl_down_sync(0xffffffffu, s, off);
    if ((t & 31) == 0) wsum[t >> 5] = s;
    __syncthreads();
    if (t == 0) {
        int tot = 0;
        for (int i = 0; i < 8; i++) tot += wsum[i];
        g_bsum[b] = tot;
    }
}

__global__ void scan_top_kernel() {
    if (threadIdx.x == 0 && blockIdx.x == 0) {
        int acc = 0;
        for (int b = 0; b < NSCAN_BLK; b++) { g_btop[b] = acc; acc += g_bsum[b]; }
    }
}

__global__ __launch_bounds__(256)
void scan_down_kernel() {
    __shared__ int wsum[8];
    int b = blockIdx.x, t = threadIdx.x;
    int lane = t & 31, w = t >> 5;
    int i0 = b * SCAN_CHUNK + t * 4;
    int v[4];
#pragma unroll
    for (int j = 0; j < 4; j++)
        v[j] = (i0 + j < N_NODES) ? g_cnt[i0 + j] : 0;
    int tsum = v[0] + v[1] + v[2] + v[3];
    int s = tsum;
    for (int off = 1; off < 32; off <<= 1) {
        int n = __shfl_up_sync(0xffffffffu, s, off);
        if (lane >= off) s += n;
    }
    if (lane == 31) wsum[w] = s;
    __syncthreads();
    if (w == 0) {
        int ws = (lane < 8) ? wsum[lane] : 0;
        for (int off = 1; off < 8; off <<= 1) {
            int n = __shfl_up_sync(0xffffffffu, ws, off);
            if (lane >= off) ws += n;
        }
        if (lane < 8) wsum[lane] = ws;
    }
    __syncthreads();
    int excl = ((w == 0) ? 0 : wsum[w - 1]) + (s - tsum) + g_btop[b];
#pragma unroll
    for (int j = 0; j < 4; j++) {
        if (i0 + j < N_NODES) { g_rowptr[i0 + j] = excl; g_wp[i0 + j] = excl; }
        excl += v[j];
    }
}

// ---------------------------------------------------------------------------
// CSR build stage 3: place dst indices into per-src segments
// ---------------------------------------------------------------------------
__global__ __launch_bounds__(256)
void fill_kernel(const void* __restrict__ adj) {
    int e = blockIdx.x * blockDim.x + threadIdx.x;
    if (e >= N_EDGES) return;
    long long s, d;
    if (g_idx_is64) {
        const long long* a = (const long long*)adj;
        s = __ldg(a + e); d = __ldg(a + N_EDGES + e);
    } else {
        const int* a = (const int*)adj;
        s = __ldg(a + e); d = __ldg(a + N_EDGES + e);
    }
    if ((unsigned long long)s >= N_NODES) return;
    if ((unsigned long long)d >= N_NODES) d = 0;   // never happens; keep safe
    int pos = atomicAdd(&g_wp[(int)s], 1);
    g_dst[pos] = (int)d;
}

// ---------------------------------------------------------------------------
// GEMM: g_Y = X @ W. 128x128 tile per block, BK=16, 8x8 register tile per
// thread, FFMA2 packed math. X stored k-major DUPLICATED in smem so the
// (x,x) f32x2 operand loads directly as u64 (no packing in inner loop);
// W f32x2 pairs come straight from LDS.128 register pairs.
// ---------------------------------------------------------------------------
#define BM 128
#define BK 16
#define XDUP 268   // 2*128 + 12 pad (floats per k-row)
__global__ __launch_bounds__(256)
void gemm_kernel(const float* __restrict__ X, const float* __restrict__ W) {
    __shared__ float sXd[BK * XDUP];   // 17152 B
    __shared__ float sW[BK * D];       //  8192 B

    const int tid  = threadIdx.x;
    const int tx   = tid & 15;         // cols tx*8 .. +7
    const int ty   = tid >> 4;         // rows ty*8 .. +7
    const int row0 = blockIdx.x * BM;

    u64 acc[8][4];
#pragma unroll
    for (int r = 0; r < 8; r++)
#pragma unroll
        for (int c = 0; c < 4; c++) acc[r][c] = 0ull;

    for (int kt = 0; kt < D; kt += BK) {
        // X tile: 128 rows x 16 k, transposed + duplicated
#pragma unroll
        for (int t = 0; t < 2; t++) {
            int idx = tid + t * 256;
            int row = idx >> 2;
            int kq  = idx & 3;
            int gr  = row0 + row; if (gr >= N_NODES) gr = N_NODES - 1;
            float4 xv = reinterpret_cast<const float4*>(X)
                            [(size_t)gr * 32 + (kt >> 2) + kq];
            u64 p;
            PACK_DUP(p, xv.x);
            *reinterpret_cast<u64*>(sXd + (kq * 4 + 0) * XDUP + 2 * row) = p;
            PACK_DUP(p, xv.y);
            *reinterpret_cast<u64*>(sXd + (kq * 4 + 1) * XDUP + 2 * row) = p;
            PACK_DUP(p, xv.z);
            *reinterpret_cast<u64*>(sXd + (kq * 4 + 2) * XDUP + 2 * row) = p;
            PACK_DUP(p, xv.w);
            *reinterpret_cast<u64*>(sXd + (kq * 4 + 3) * XDUP + 2 * row) = p;
        }
        // W tile: 16 k x 128 cols
#pragma unroll
        for (int t = 0; t < 2; t++) {
            int idx = tid + t * 256;
            reinterpret_cast<float4*>(sW)[idx] =
                reinterpret_cast<const float4*>(W)
                    [(size_t)(kt + (idx >> 5)) * 32 + (idx & 31)];
        }
        __syncthreads();

#pragma unroll
        for (int kk = 0; kk < BK; kk++) {
            const ulonglong2* xp =
                reinterpret_cast<const ulonglong2*>(sXd + kk * XDUP + ty * 16);
            ulonglong2 xa = xp[0], xb = xp[1], xc = xp[2], xd = xp[3];
            u64 xr[8] = {xa.x, xa.y, xb.x, xb.y, xc.x, xc.y, xd.x, xd.y};
            const ulonglong2* wk =
                reinterpret_cast<const ulonglong2*>(sW + kk * D);
            ulonglong2 wA = wk[tx * 2], wB = wk[tx * 2 + 1];
            u64 wp[4] = {wA.x, wA.y, wB.x, wB.y};
#pragma unroll
            for (int r = 0; r < 8; r++)
#pragma unroll
                for (int c = 0; c < 4; c++)
                    FMA2(acc[r][c], xr[r], wp[c], acc[r][c]);
        }
        __syncthreads();
    }

#pragma unroll
    for (int r = 0; r < 8; r++) {
        int grow = row0 + ty * 8 + r;
        if (grow < N_NODES) {
            ulonglong2 v0; v0.x = acc[r][0]; v0.y = acc[r][1];
            ulonglong2 v1; v1.x = acc[r][2]; v1.y = acc[r][3];
            float* yr = g_Y + (size_t)grow * D + tx * 8;
            *reinterpret_cast<ulonglong2*>(yr)     = v0;
            *reinterpret_cast<ulonglong2*>(yr + 4) = v1;
        }
    }
}

// ---------------------------------------------------------------------------
// Aggregate: one warp per node. Warp-batched index loads (32 per LDG) then
// shfl-broadcast; each lane accumulates 4 columns over all neighbors and
// writes the mean once. No atomics, no separate zero/divide.
// ---------------------------------------------------------------------------
__global__ __launch_bounds__(256)
void agg_kernel(float* __restrict__ out) {
    int gt   = blockIdx.x * blockDim.x + threadIdx.x;
    int node = gt >> 5;
    int lane = gt & 31;
    if (node >= N_NODES) return;

    int e0  = g_rowptr[node];
    int deg = g_cnt[node];

    float4 acc = make_float4(0.f, 0.f, 0.f, 0.f);
    for (int base = 0; base < deg; base += 32) {
        int idx = (base + lane < deg) ? __ldg(g_dst + e0 + base + lane) : 0;
        int m = deg - base; if (m > 32) m = 32;
#pragma unroll 4
        for (int j = 0; j < m; j++) {
            int dn = __shfl_sync(0xffffffffu, idx, j);
            float4 v = *reinterpret_cast<const float4*>(
                g_Y + (size_t)dn * D + lane * 4);
            acc.x += v.x; acc.y += v.y; acc.z += v.z; acc.w += v.w;
        }
    }
    float inv = 1.0f / fmaxf((float)deg, 1.0f);
    float4 r = make_float4(acc.x * inv, acc.y * inv, acc.z * inv, acc.w * inv);
    *reinterpret_cast<float4*>(out + (size_t)node * D + lane * 4) = r;
}

// ---------------------------------------------------------------------------
extern "C" void kernel_launch(void* const* d_in, const int* in_sizes, int n_in,
                              void* d_out, int out_size) {
    // Identify inputs by element count (ordering-proof)
    const float* X   = nullptr;
    const void*  adj = nullptr;
    const float* W   = nullptr;
    for (int i = 0; i < n_in; i++) {
        if (in_sizes[i] == N_NODES * D)      X   = (const float*)d_in[i];
        else if (in_sizes[i] == 2 * N_EDGES) adj = d_in[i];
        else if (in_sizes[i] == D * D)       W   = (const float*)d_in[i];
    }
    float* out = (float*)d_out;

    detect_kernel<<<1, 32>>>((const unsigned int*)adj);
    zero_cnt_kernel<<<(N_NODES + 255) / 256, 256>>>();
    hist_kernel<<<(N_EDGES + 255) / 256, 256>>>(adj);
    scan_block_kernel<<<NSCAN_BLK, 256>>>();
    scan_top_kernel<<<1, 32>>>();
    scan_down_kernel<<<NSCAN_BLK, 256>>>();
    fill_kernel<<<(N_EDGES + 255) / 256, 256>>>(adj);
    gemm_kernel<<<(N_NODES + BM - 1) / BM, 256>>>(X, W);
    agg_kernel<<<(N_NODES * 32 + 255) / 256, 256>>>(out);
}

// round 12
// speedup vs baseline: 2.1964x; 1.0791x over previous
#include <cuda_runtime.h>
#include <cstdint>

#define N_NODES 100000
#define N_EDGES 1600000
#define D 128
#define SCAN_CHUNK 1024
#define NSCAN_BLK ((N_NODES + SCAN_CHUNK - 1) / SCAN_CHUNK)   // 98

typedef unsigned long long u64;

// Scratch — device-code references ONLY (host-arg shadow-address bug, R3-R6).
__device__ float g_Y[(size_t)N_NODES * D];   // X @ W
__device__ int   g_cnt[N_NODES];             // degree histogram
__device__ int   g_rowptr[N_NODES];          // CSR row starts
__device__ int   g_wp[N_NODES];              // fill write pointers
__device__ int   g_dst[N_EDGES];             // dst indices grouped by src
__device__ int   g_bsum[NSCAN_BLK];
__device__ int   g_btop[NSCAN_BLK];
__device__ int   g_idx_is64;

// Packed-f32 FMA (B300 FFMA2 — only reachable via PTX)
#define PACK_DUP(dst, x) \
    asm("mov.b64 %0, {%1, %1};" : "=l"(dst) : "f"(x))
#define FMA2(d, a, b, c) \
    asm("fma.rn.f32x2 %0, %1, %2, %3;" : "=l"(d) : "l"(a), "l"(b), "l"(c))

// ---------------------------------------------------------------------------
// init: zero g_cnt (grid-stride) + dtype detect (block 0 thread 0).
// int64 values < 2^32 -> all odd 32-bit words are 0 (p(misdetect) ~ 1e-320).
// ---------------------------------------------------------------------------
__global__ void init_kernel(const unsigned int* __restrict__ adj_raw) {
    int i = blockIdx.x * blockDim.x + threadIdx.x;
    if (i < N_NODES) g_cnt[i] = 0;
    if (i == 0) {
        int is64 = 1;
        for (int k = 1; k < 128; k += 2)
            if (adj_raw[k] != 0u) { is64 = 0; break; }
        g_idx_is64 = is64;
    }
}

// ---------------------------------------------------------------------------
// CSR stage 1: histogram src degrees
// ---------------------------------------------------------------------------
__global__ __launch_bounds__(256)
void hist_kernel(const void* __restrict__ adj) {
    int e = blockIdx.x * blockDim.x + threadIdx.x;
    if (e >= N_EDGES) return;
    long long s = g_idx_is64 ? __ldg((const long long*)adj + e)
                             : (long long)__ldg((const int*)adj + e);
    if ((unsigned long long)s < N_NODES)
        atomicAdd(&g_cnt[(int)s], 1);
}

// ---------------------------------------------------------------------------
// CSR stage 2: exclusive scan of g_cnt (3 kernels)
// ---------------------------------------------------------------------------
__global__ __launch_bounds__(256)
void scan_block_kernel() {
    __shared__ int wsum[8];
    int b = blockIdx.x, t = threadIdx.x;
    int i0 = b * SCAN_CHUNK + t * 4;
    int s = 0;
#pragma unroll
    for (int j = 0; j < 4; j++)
        s += (i0 + j < N_NODES) ? g_cnt[i0 + j] : 0;
    for (int off = 16; off; off >>= 1)
        s += __shfl_down_sync(0xffffffffu, s, off);
    if ((t & 31) == 0) wsum[t >> 5] = s;
    __syncthreads();
    if (t == 0) {
        int tot = 0;
        for (int i = 0; i < 8; i++) tot += wsum[i];
        g_bsum[b] = tot;
    }
}

__global__ void scan_top_kernel() {
    if (threadIdx.x == 0 && blockIdx.x == 0) {
        int acc = 0;
        for (int b = 0; b < NSCAN_BLK; b++) { g_btop[b] = acc; acc += g_bsum[b]; }
    }
}

__global__ __launch_bounds__(256)
void scan_down_kernel() {
    __shared__ int wsum[8];
    int b = blockIdx.x, t = threadIdx.x;
    int lane = t & 31, w = t >> 5;
    int i0 = b * SCAN_CHUNK + t * 4;
    int v[4];
#pragma unroll
    for (int j = 0; j < 4; j++)
        v[j] = (i0 + j < N_NODES) ? g_cnt[i0 + j] : 0;
    int tsum = v[0] + v[1] + v[2] + v[3];
    int s = tsum;
    for (int off = 1; off < 32; off <<= 1) {
        int n = __shfl_up_sync(0xffffffffu, s, off);
        if (lane >= off) s += n;
    }
    if (lane == 31) wsum[w] = s;
    __syncthreads();
    if (w == 0) {
        int ws = (lane < 8) ? wsum[lane] : 0;
        for (int off = 1; off < 8; off <<= 1) {
            int n = __shfl_up_sync(0xffffffffu, ws, off);
            if (lane >= off) ws += n;
        }
        if (lane < 8) wsum[lane] = ws;
    }
    __syncthreads();
    int excl = ((w == 0) ? 0 : wsum[w - 1]) + (s - tsum) + g_btop[b];
#pragma unroll
    for (int j = 0; j < 4; j++) {
        if (i0 + j < N_NODES) { g_rowptr[i0 + j] = excl; g_wp[i0 + j] = excl; }
        excl += v[j];
    }
}

// ---------------------------------------------------------------------------
// CSR stage 3: place dst indices into per-src segments
// ---------------------------------------------------------------------------
__global__ __launch_bounds__(256)
void fill_kernel(const void* __restrict__ adj) {
    int e = blockIdx.x * blockDim.x + threadIdx.x;
    if (e >= N_EDGES) return;
    long long s, d;
    if (g_idx_is64) {
        const long long* a = (const long long*)adj;
        s = __ldg(a + e); d = __ldg(a + N_EDGES + e);
    } else {
        const int* a = (const int*)adj;
        s = __ldg(a + e); d = __ldg(a + N_EDGES + e);
    }
    if ((unsigned long long)s >= N_NODES) return;
    if ((unsigned long long)d >= N_NODES) d = 0;   // never happens; keep safe
    int pos = atomicAdd(&g_wp[(int)s], 1);
    g_dst[pos] = (int)d;
}

// ---------------------------------------------------------------------------
// GEMM: g_Y = X @ W. 128x128 tile, BK=16, 8x8 register tile, FFMA2.
// Software-pipelined: chunk c+1 fetched into registers during compute on c.
// ---------------------------------------------------------------------------
#define BM 128
#define BK 16
#define XDUP 268   // 2*128 + 12 pad (floats per k-row)
#define NCHUNK (D / BK)
__global__ __launch_bounds__(256)
void gemm_kernel(const float* __restrict__ X, const float* __restrict__ W) {
    __shared__ float sXd[BK * XDUP];   // 17152 B
    __shared__ float sW[BK * D];       //  8192 B

    const int tid  = threadIdx.x;
    const int tx   = tid & 15;         // cols tx*8 .. +7
    const int ty   = tid >> 4;         // rows ty*8 .. +7
    const int row0 = blockIdx.x * BM;

    // Per-thread fetch coordinates (2 float4 each for X and W)
    const int xrow = tid >> 2;           // 0..63 (and +64 for t=1)
    const int xkq  = tid & 3;            // k-quad within chunk
    int xg0 = row0 + xrow;       if (xg0 >= N_NODES) xg0 = N_NODES - 1;
    int xg1 = row0 + xrow + 64;  if (xg1 >= N_NODES) xg1 = N_NODES - 1;

    float4 xf[2], wf[2];
    // fetch chunk 0
    xf[0] = reinterpret_cast<const float4*>(X)[(size_t)xg0 * 32 + xkq];
    xf[1] = reinterpret_cast<const float4*>(X)[(size_t)xg1 * 32 + xkq];
    wf[0] = reinterpret_cast<const float4*>(W)[(size_t)(tid >> 5) * 32 + (tid & 31)];
    wf[1] = reinterpret_cast<const float4*>(W)[(size_t)((tid + 256) >> 5) * 32 + (tid & 31)];

    u64 acc[8][4];
#pragma unroll
    for (int r = 0; r < 8; r++)
#pragma unroll
        for (int c = 0; c < 4; c++) acc[r][c] = 0ull;

    // store chunk 0 to smem
    {
        u64 p;
        int rows[2] = {xrow, xrow + 64};
#pragma unroll
        for (int t = 0; t < 2; t++) {
            PACK_DUP(p, xf[t].x);
            *reinterpret_cast<u64*>(sXd + (xkq * 4 + 0) * XDUP + 2 * rows[t]) = p;
            PACK_DUP(p, xf[t].y);
            *reinterpret_cast<u64*>(sXd + (xkq * 4 + 1) * XDUP + 2 * rows[t]) = p;
            PACK_DUP(p, xf[t].z);
            *reinterpret_cast<u64*>(sXd + (xkq * 4 + 2) * XDUP + 2 * rows[t]) = p;
            PACK_DUP(p, xf[t].w);
            *reinterpret_cast<u64*>(sXd + (xkq * 4 + 3) * XDUP + 2 * rows[t]) = p;
        }
        reinterpret_cast<float4*>(sW)[tid]       = wf[0];
        reinterpret_cast<float4*>(sW)[tid + 256] = wf[1];
    }
    __syncthreads();

    for (int c = 0; c < NCHUNK; c++) {
        // prefetch chunk c+1 into registers (global latency hidden by compute)
        if (c + 1 < NCHUNK) {
            int kq = ((c + 1) * BK >> 2) + xkq;
            xf[0] = reinterpret_cast<const float4*>(X)[(size_t)xg0 * 32 + kq];
            xf[1] = reinterpret_cast<const float4*>(X)[(size_t)xg1 * 32 + kq];
            int kr = (c + 1) * BK;
            wf[0] = reinterpret_cast<const float4*>(W)
                        [(size_t)(kr + (tid >> 5)) * 32 + (tid & 31)];
            wf[1] = reinterpret_cast<const float4*>(W)
                        [(size_t)(kr + ((tid + 256) >> 5)) * 32 + (tid & 31)];
        }

#pragma unroll
        for (int kk = 0; kk < BK; kk++) {
            const ulonglong2* xp =
                reinterpret_cast<const ulonglong2*>(sXd + kk * XDUP + ty * 16);
            ulonglong2 xa = xp[0], xb = xp[1], xc = xp[2], xd = xp[3];
            u64 xr[8] = {xa.x, xa.y, xb.x, xb.y, xc.x, xc.y, xd.x, xd.y};
            const ulonglong2* wk =
                reinterpret_cast<const ulonglong2*>(sW + kk * D);
            ulonglong2 wA = wk[tx * 2], wB = wk[tx * 2 + 1];
            u64 wp[4] = {wA.x, wA.y, wB.x, wB.y};
#pragma unroll
            for (int r = 0; r < 8; r++)
#pragma unroll
                for (int cc = 0; cc < 4; cc++)
                    FMA2(acc[r][cc], xr[r], wp[cc], acc[r][cc]);
        }

        if (c + 1 < NCHUNK) {
            __syncthreads();   // everyone done reading smem chunk c
            u64 p;
            int rows[2] = {xrow, xrow + 64};
#pragma unroll
            for (int t = 0; t < 2; t++) {
                PACK_DUP(p, xf[t].x);
                *reinterpret_cast<u64*>(sXd + (xkq * 4 + 0) * XDUP + 2 * rows[t]) = p;
                PACK_DUP(p, xf[t].y);
                *reinterpret_cast<u64*>(sXd + (xkq * 4 + 1) * XDUP + 2 * rows[t]) = p;
                PACK_DUP(p, xf[t].z);
                *reinterpret_cast<u64*>(sXd + (xkq * 4 + 2) * XDUP + 2 * rows[t]) = p;
                PACK_DUP(p, xf[t].w);
                *reinterpret_cast<u64*>(sXd + (xkq * 4 + 3) * XDUP + 2 * rows[t]) = p;
            }
            reinterpret_cast<float4*>(sW)[tid]       = wf[0];
            reinterpret_cast<float4*>(sW)[tid + 256] = wf[1];
            __syncthreads();
        }
    }

#pragma unroll
    for (int r = 0; r < 8; r++) {
        int grow = row0 + ty * 8 + r;
        if (grow < N_NODES) {
            ulonglong2 v0; v0.x = acc[r][0]; v0.y = acc[r][1];
            ulonglong2 v1; v1.x = acc[r][2]; v1.y = acc[r][3];
            float* yr = g_Y + (size_t)grow * D + tx * 8;
            *reinterpret_cast<ulonglong2*>(yr)     = v0;
            *reinterpret_cast<ulonglong2*>(yr + 4) = v1;
        }
    }
}

// ---------------------------------------------------------------------------
// Aggregate: one warp per node; warp-batched index loads + shfl broadcast;
// mean applied at write. No atomics.
// ---------------------------------------------------------------------------
__global__ __launch_bounds__(256)
void agg_kernel(float* __restrict__ out) {
    int gt   = blockIdx.x * blockDim.x + threadIdx.x;
    int node = gt >> 5;
    int lane = gt & 31;
    if (node >= N_NODES) return;

    int e0  = g_rowptr[node];
    int deg = g_cnt[node];

    float4 acc = make_float4(0.f, 0.f, 0.f, 0.f);
    for (int base = 0; base < deg; base += 32) {
        int idx = (base + lane < deg) ? __ldg(g_dst + e0 + base + lane) : 0;
        int m = deg - base; if (m > 32) m = 32;
#pragma unroll 4
        for (int j = 0; j < m; j++) {
            int dn = __shfl_sync(0xffffffffu, idx, j);
            float4 v = *reinterpret_cast<const float4*>(
                g_Y + (size_t)dn * D + lane * 4);
            acc.x += v.x; acc.y += v.y; acc.z += v.z; acc.w += v.w;
        }
    }
    float inv = 1.0f / fmaxf((float)deg, 1.0f);
    float4 r = make_float4(acc.x * inv, acc.y * inv, acc.z * inv, acc.w * inv);
    *reinterpret_cast<float4*>(out + (size_t)node * D + lane * 4) = r;
}

// ---------------------------------------------------------------------------
extern "C" void kernel_launch(void* const* d_in, const int* in_sizes, int n_in,
                              void* d_out, int out_size) {
    // Identify inputs by element count (ordering-proof)
    const float* X   = nullptr;
    const void*  adj = nullptr;
    const float* W   = nullptr;
    for (int i = 0; i < n_in; i++) {
        if (in_sizes[i] == N_NODES * D)      X   = (const float*)d_in[i];
        else if (in_sizes[i] == 2 * N_EDGES) adj = d_in[i];
        else if (in_sizes[i] == D * D)       W   = (const float*)d_in[i];
    }
    float* out = (float*)d_out;

    // Fork: GEMM on side stream, CSR build on main stream, join before agg.
    // kernel_launch runs only for correctness + capture (not per replay),
    // so per-call creation of stream/events does not accumulate.
    cudaStream_t s1;
    cudaStreamCreateWithFlags(&s1, cudaStreamNonBlocking);
    cudaEvent_t e0, e1;
    cudaEventCreateWithFlags(&e0, cudaEventDisableTiming);
    cudaEventCreateWithFlags(&e1, cudaEventDisableTiming);

    cudaEventRecord(e0, 0);
    cudaStreamWaitEvent(s1, e0, 0);
    gemm_kernel<<<(N_NODES + BM - 1) / BM, 256, 0, s1>>>(X, W);
    cudaEventRecord(e1, s1);

    // CSR build chain (main stream, concurrent with GEMM)
    init_kernel<<<(N_NODES + 255) / 256, 256>>>((const unsigned int*)adj);
    hist_kernel<<<(N_EDGES + 255) / 256, 256>>>(adj);
    scan_block_kernel<<<NSCAN_BLK, 256>>>();
    scan_top_kernel<<<1, 32>>>();
    scan_down_kernel<<<NSCAN_BLK, 256>>>();
    fill_kernel<<<(N_EDGES + 255) / 256, 256>>>(adj);

    cudaStreamWaitEvent(0, e1, 0);   // join GEMM
    agg_kernel<<<(N_NODES * 32 + 255) / 256, 256>>>(out);
}

// round 14
// speedup vs baseline: 2.5477x; 1.1600x over previous
#include <cuda_runtime.h>
#include <cuda_fp16.h>
#include <cstdint>

#define N_NODES 100000
#define N_EDGES 1600000
#define D 128
#define SCAN_CHUNK 1024
#define NSCAN_BLK ((N_NODES + SCAN_CHUNK - 1) / SCAN_CHUNK)   // 98

typedef unsigned long long u64;

// Scratch — device-code references ONLY (host-arg shadow-address bug, R3-R6).
__device__ __half g_Yh[(size_t)N_NODES * D];  // X @ W in fp16 (25.6 MB)
__device__ int    g_cnt[N_NODES];             // degree histogram
__device__ int    g_rowptr[N_NODES];          // CSR row starts
__device__ int    g_wp[N_NODES];              // fill write pointers
__device__ int    g_dst[N_EDGES];             // dst indices grouped by src
__device__ int    g_bsum[NSCAN_BLK];
__device__ int    g_btop[NSCAN_BLK];
__device__ int    g_idx_is64;

// Packed-f32 ops (B300 FFMA2 — only reachable via PTX)
#define PACK_DUP(dst, x) \
    asm("mov.b64 %0, {%1, %1};" : "=l"(dst) : "f"(x))
#define FMA2(d, a, b, c) \
    asm("fma.rn.f32x2 %0, %1, %2, %3;" : "=l"(d) : "l"(a), "l"(b), "l"(c))
#define UNPACK2(lo, hi, p) \
    asm("mov.b64 {%0, %1}, %2;" : "=f"(lo), "=f"(hi) : "l"(p))

// Bit casts (version-proof, no exotic intrinsics)
static __device__ __forceinline__ unsigned h2_to_u32(__half2 h) {
    union { __half2 h; unsigned u; } c; c.h = h; return c.u;
}
static __device__ __forceinline__ __half2 u32_to_h2(unsigned u) {
    union { unsigned u; __half2 h; } c; c.u = u; return c.h;
}

// ---------------------------------------------------------------------------
// init: zero g_cnt + dtype detect (int64 values < 2^32 -> odd words all 0).
// ---------------------------------------------------------------------------
__global__ void init_kernel(const unsigned int* __restrict__ adj_raw) {
    int i = blockIdx.x * blockDim.x + threadIdx.x;
    if (i < N_NODES) g_cnt[i] = 0;
    if (i == 0) {
        int is64 = 1;
        for (int k = 1; k < 128; k += 2)
            if (adj_raw[k] != 0u) { is64 = 0; break; }
        g_idx_is64 = is64;
    }
}

// ---------------------------------------------------------------------------
// CSR stage 1: histogram src degrees
// ---------------------------------------------------------------------------
__global__ __launch_bounds__(256)
void hist_kernel(const void* __restrict__ adj) {
    int e = blockIdx.x * blockDim.x + threadIdx.x;
    if (e >= N_EDGES) return;
    long long s = g_idx_is64 ? __ldg((const long long*)adj + e)
                             : (long long)__ldg((const int*)adj + e);
    if ((unsigned long long)s < N_NODES)
        atomicAdd(&g_cnt[(int)s], 1);
}

// ---------------------------------------------------------------------------
// CSR stage 2: exclusive scan of g_cnt (3 kernels)
// ---------------------------------------------------------------------------
__global__ __launch_bounds__(256)
void scan_block_kernel() {
    __shared__ int wsum[8];
    int b = blockIdx.x, t = threadIdx.x;
    int i0 = b * SCAN_CHUNK + t * 4;
    int s = 0;
#pragma unroll
    for (int j = 0; j < 4; j++)
        s += (i0 + j < N_NODES) ? g_cnt[i0 + j] : 0;
    for (int off = 16; off; off >>= 1)
        s += __shfl_down_sync(0xffffffffu, s, off);
    if ((t & 31) == 0) wsum[t >> 5] = s;
    __syncthreads();
    if (t == 0) {
        int tot = 0;
        for (int i = 0; i < 8; i++) tot += wsum[i];
        g_bsum[b] = tot;
    }
}

__global__ void scan_top_kernel() {
    if (threadIdx.x == 0 && blockIdx.x == 0) {
        int acc = 0;
        for (int b = 0; b < NSCAN_BLK; b++) { g_btop[b] = acc; acc += g_bsum[b]; }
    }
}

__global__ __launch_bounds__(256)
void scan_down_kernel() {
    __shared__ int wsum[8];
    int b = blockIdx.x, t = threadIdx.x;
    int lane = t & 31, w = t >> 5;
    int i0 = b * SCAN_CHUNK + t * 4;
    int v[4];
#pragma unroll
    for (int j = 0; j < 4; j++)
        v[j] = (i0 + j < N_NODES) ? g_cnt[i0 + j] : 0;
    int tsum = v[0] + v[1] + v[2] + v[3];
    int s = tsum;
    for (int off = 1; off < 32; off <<= 1) {
        int n = __shfl_up_sync(0xffffffffu, s, off);
        if (lane >= off) s += n;
    }
    if (lane == 31) wsum[w] = s;
    __syncthreads();
    if (w == 0) {
        int ws = (lane < 8) ? wsum[lane] : 0;
        for (int off = 1; off < 8; off <<= 1) {
            int n = __shfl_up_sync(0xffffffffu, ws, off);
            if (lane >= off) ws += n;
        }
        if (lane < 8) wsum[lane] = ws;
    }
    __syncthreads();
    int excl = ((w == 0) ? 0 : wsum[w - 1]) + (s - tsum) + g_btop[b];
#pragma unroll
    for (int j = 0; j < 4; j++) {
        if (i0 + j < N_NODES) { g_rowptr[i0 + j] = excl; g_wp[i0 + j] = excl; }
        excl += v[j];
    }
}

// ---------------------------------------------------------------------------
// CSR stage 3: place dst indices into per-src segments
// ---------------------------------------------------------------------------
__global__ __launch_bounds__(256)
void fill_kernel(const void* __restrict__ adj) {
    int e = blockIdx.x * blockDim.x + threadIdx.x;
    if (e >= N_EDGES) return;
    long long s, d;
    if (g_idx_is64) {
        const long long* a = (const long long*)adj;
        s = __ldg(a + e); d = __ldg(a + N_EDGES + e);
    } else {
        const int* a = (const int*)adj;
        s = __ldg(a + e); d = __ldg(a + N_EDGES + e);
    }
    if ((unsigned long long)s >= N_NODES) return;
    if ((unsigned long long)d >= N_NODES) d = 0;   // never happens; keep safe
    int pos = atomicAdd(&g_wp[(int)s], 1);
    g_dst[pos] = (int)d;
}

// ---------------------------------------------------------------------------
// GEMM: g_Yh = fp16(X @ W). 128x128 tile, BK=16, 8x8 register tile, FFMA2,
// software-pipelined (chunk c+1 fetched to registers during compute on c).
// ---------------------------------------------------------------------------
#define BM 128
#define BK 16
#define XDUP 268   // 2*128 + 12 pad (floats per k-row)
#define NCHUNK (D / BK)
__global__ __launch_bounds__(256)
void gemm_kernel(const float* __restrict__ X, const float* __restrict__ W) {
    __shared__ float sXd[BK * XDUP];   // 17152 B
    __shared__ float sW[BK * D];       //  8192 B

    const int tid  = threadIdx.x;
    const int tx   = tid & 15;         // cols tx*8 .. +7
    const int ty   = tid >> 4;         // rows ty*8 .. +7
    const int row0 = blockIdx.x * BM;

    const int xrow = tid >> 2;         // 0..63 (and +64)
    const int xkq  = tid & 3;
    int xg0 = row0 + xrow;       if (xg0 >= N_NODES) xg0 = N_NODES - 1;
    int xg1 = row0 + xrow + 64;  if (xg1 >= N_NODES) xg1 = N_NODES - 1;

    float4 xf[2], wf[2];
    xf[0] = reinterpret_cast<const float4*>(X)[(size_t)xg0 * 32 + xkq];
    xf[1] = reinterpret_cast<const float4*>(X)[(size_t)xg1 * 32 + xkq];
    wf[0] = reinterpret_cast<const float4*>(W)[(size_t)(tid >> 5) * 32 + (tid & 31)];
    wf[1] = reinterpret_cast<const float4*>(W)[(size_t)((tid + 256) >> 5) * 32 + (tid & 31)];

    u64 acc[8][4];
#pragma unroll
    for (int r = 0; r < 8; r++)
#pragma unroll
        for (int c = 0; c < 4; c++) acc[r][c] = 0ull;

    {
        u64 p;
        int rows[2] = {xrow, xrow + 64};
#pragma unroll
        for (int t = 0; t < 2; t++) {
            PACK_DUP(p, xf[t].x);
            *reinterpret_cast<u64*>(sXd + (xkq * 4 + 0) * XDUP + 2 * rows[t]) = p;
            PACK_DUP(p, xf[t].y);
            *reinterpret_cast<u64*>(sXd + (xkq * 4 + 1) * XDUP + 2 * rows[t]) = p;
            PACK_DUP(p, xf[t].z);
            *reinterpret_cast<u64*>(sXd + (xkq * 4 + 2) * XDUP + 2 * rows[t]) = p;
            PACK_DUP(p, xf[t].w);
            *reinterpret_cast<u64*>(sXd + (xkq * 4 + 3) * XDUP + 2 * rows[t]) = p;
        }
        reinterpret_cast<float4*>(sW)[tid]       = wf[0];
        reinterpret_cast<float4*>(sW)[tid + 256] = wf[1];
    }
    __syncthreads();

    for (int c = 0; c < NCHUNK; c++) {
        if (c + 1 < NCHUNK) {
            int kq = ((c + 1) * BK >> 2) + xkq;
            xf[0] = reinterpret_cast<const float4*>(X)[(size_t)xg0 * 32 + kq];
            xf[1] = reinterpret_cast<const float4*>(X)[(size_t)xg1 * 32 + kq];
            int kr = (c + 1) * BK;
            wf[0] = reinterpret_cast<const float4*>(W)
                        [(size_t)(kr + (tid >> 5)) * 32 + (tid & 31)];
            wf[1] = reinterpret_cast<const float4*>(W)
                        [(size_t)(kr + ((tid + 256) >> 5)) * 32 + (tid & 31)];
        }

#pragma unroll
        for (int kk = 0; kk < BK; kk++) {
            const ulonglong2* xp =
                reinterpret_cast<const ulonglong2*>(sXd + kk * XDUP + ty * 16);
            ulonglong2 xa = xp[0], xb = xp[1], xc = xp[2], xd = xp[3];
            u64 xr[8] = {xa.x, xa.y, xb.x, xb.y, xc.x, xc.y, xd.x, xd.y};
            const ulonglong2* wk =
                reinterpret_cast<const ulonglong2*>(sW + kk * D);
            ulonglong2 wA = wk[tx * 2], wB = wk[tx * 2 + 1];
            u64 wp[4] = {wA.x, wA.y, wB.x, wB.y};
#pragma unroll
            for (int r = 0; r < 8; r++)
#pragma unroll
                for (int cc = 0; cc < 4; cc++)
                    FMA2(acc[r][cc], xr[r], wp[cc], acc[r][cc]);
        }

        if (c + 1 < NCHUNK) {
            __syncthreads();
            u64 p;
            int rows[2] = {xrow, xrow + 64};
#pragma unroll
            for (int t = 0; t < 2; t++) {
                PACK_DUP(p, xf[t].x);
                *reinterpret_cast<u64*>(sXd + (xkq * 4 + 0) * XDUP + 2 * rows[t]) = p;
                PACK_DUP(p, xf[t].y);
                *reinterpret_cast<u64*>(sXd + (xkq * 4 + 1) * XDUP + 2 * rows[t]) = p;
                PACK_DUP(p, xf[t].z);
                *reinterpret_cast<u64*>(sXd + (xkq * 4 + 2) * XDUP + 2 * rows[t]) = p;
                PACK_DUP(p, xf[t].w);
                *reinterpret_cast<u64*>(sXd + (xkq * 4 + 3) * XDUP + 2 * rows[t]) = p;
            }
            reinterpret_cast<float4*>(sW)[tid]       = wf[0];
            reinterpret_cast<float4*>(sW)[tid + 256] = wf[1];
            __syncthreads();
        }
    }

    // Epilogue: packed f32x2 accumulators -> half2, 16B store per row slice
#pragma unroll
    for (int r = 0; r < 8; r++) {
        int grow = row0 + ty * 8 + r;
        if (grow < N_NODES) {
            uint4 hv;
            float lo, hi;
            UNPACK2(lo, hi, acc[r][0]); hv.x = h2_to_u32(__floats2half2_rn(lo, hi));
            UNPACK2(lo, hi, acc[r][1]); hv.y = h2_to_u32(__floats2half2_rn(lo, hi));
            UNPACK2(lo, hi, acc[r][2]); hv.z = h2_to_u32(__floats2half2_rn(lo, hi));
            UNPACK2(lo, hi, acc[r][3]); hv.w = h2_to_u32(__floats2half2_rn(lo, hi));
            *reinterpret_cast<uint4*>(g_Yh + (size_t)grow * D + tx * 8) = hv;
        }
    }
}

// ---------------------------------------------------------------------------
// Aggregate: one warp per node, TWO edges per iteration (one per half-warp).
// Row = 256B fp16: 16 lanes x uint4. Lane (h,cg) = (lane>>4, lane&15) reads
// cols cg*8..+7 of edge j+h. fp32 accumulate; cross-half-warp combine via
// shfl_xor(16); mean applied at the single fp32 write.
// ---------------------------------------------------------------------------
__global__ __launch_bounds__(256)
void agg_kernel(float* __restrict__ out) {
    int gt   = blockIdx.x * blockDim.x + threadIdx.x;
    int node = gt >> 5;
    int lane = gt & 31;
    if (node >= N_NODES) return;

    int e0  = g_rowptr[node];
    int deg = g_cnt[node];
    int h   = lane >> 4;     // half-warp id
    int cg  = lane & 15;     // col group (8 halves)

    float a[8];
#pragma unroll
    for (int i = 0; i < 8; i++) a[i] = 0.f;

    for (int base = 0; base < deg; base += 32) {
        int idx = (base + lane < deg) ? __ldg(g_dst + e0 + base + lane) : 0;
        int m = deg - base; if (m > 32) m = 32;
#pragma unroll 4
        for (int j = 0; j < m; j += 2) {
            int jj = j + h;
            int dn = __shfl_sync(0xffffffffu, idx, jj & 31);
            if (jj < m) {
                uint4 v = *reinterpret_cast<const uint4*>(
                    g_Yh + (size_t)dn * D + cg * 8);
                float2 f;
                f = __half22float2(u32_to_h2(v.x)); a[0] += f.x; a[1] += f.y;
                f = __half22float2(u32_to_h2(v.y)); a[2] += f.x; a[3] += f.y;
                f = __half22float2(u32_to_h2(v.z)); a[4] += f.x; a[5] += f.y;
                f = __half22float2(u32_to_h2(v.w)); a[6] += f.x; a[7] += f.y;
            }
        }
    }
    // combine the two half-warps (same columns, disjoint edge subsets)
#pragma unroll
    for (int i = 0; i < 8; i++)
        a[i] += __shfl_xor_sync(0xffffffffu, a[i], 16);

    float inv = 1.0f / fmaxf((float)deg, 1.0f);
    // lane (h,cg) writes cols cg*8 + h*4 .. +3
    float4 r = h ? make_float4(a[4] * inv, a[5] * inv, a[6] * inv, a[7] * inv)
                 : make_float4(a[0] * inv, a[1] * inv, a[2] * inv, a[3] * inv);
    *reinterpret_cast<float4*>(out + (size_t)node * D + cg * 8 + h * 4) = r;
}

// ---------------------------------------------------------------------------
extern "C" void kernel_launch(void* const* d_in, const int* in_sizes, int n_in,
                              void* d_out, int out_size) {
    // Identify inputs by element count (ordering-proof)
    const float* X   = nullptr;
    const void*  adj = nullptr;
    const float* W   = nullptr;
    for (int i = 0; i < n_in; i++) {
        if (in_sizes[i] == N_NODES * D)      X   = (const float*)d_in[i];
        else if (in_sizes[i] == 2 * N_EDGES) adj = d_in[i];
        else if (in_sizes[i] == D * D)       W   = (const float*)d_in[i];
    }
    float* out = (float*)d_out;

    // Fork: GEMM on side stream, CSR build on main stream, join before agg.
    cudaStream_t s1;
    cudaStreamCreateWithFlags(&s1, cudaStreamNonBlocking);
    cudaEvent_t e0, e1;
    cudaEventCreateWithFlags(&e0, cudaEventDisableTiming);
    cudaEventCreateWithFlags(&e1, cudaEventDisableTiming);

    cudaEventRecord(e0, 0);
    cudaStreamWaitEvent(s1, e0, 0);
    gemm_kernel<<<(N_NODES + BM - 1) / BM, 256, 0, s1>>>(X, W);
    cudaEventRecord(e1, s1);

    init_kernel<<<(N_NODES + 255) / 256, 256>>>((const unsigned int*)adj);
    hist_kernel<<<(N_EDGES + 255) / 256, 256>>>(adj);
    scan_block_kernel<<<NSCAN_BLK, 256>>>();
    scan_top_kernel<<<1, 32>>>();
    scan_down_kernel<<<NSCAN_BLK, 256>>>();
    fill_kernel<<<(N_EDGES + 255) / 256, 256>>>(adj);

    cudaStreamWaitEvent(0, e1, 0);   // join GEMM
    agg_kernel<<<(N_NODES * 32 + 255) / 256, 256>>>(out);
}